// round 2
// baseline (speedup 1.0000x reference)
#include <cuda_runtime.h>
#include <cstdint>
#include <cstddef>

#define TT   4096
#define EMBD 100
#define HIDN 512
#define G3   1536

// ---------------- scratch (no cudaMalloc allowed) ----------------
__device__ float g_x[TT * EMBD];            // embedded inputs      (1.6 MB)
__device__ float g_y0[TT * 1024];           // layer-0 output       (16.8 MB)
__device__ float g_gi0[2 * TT * G3];        // layer-0 input gates  (50.3 MB)
__device__ float g_gi1[2 * TT * G3];        // layer-1 input gates  (50.3 MB)

// ---------------- helpers ----------------
__device__ __forceinline__ void st_remote_f32(unsigned saddr, unsigned rank, float v) {
    asm volatile(
        "{\n\t.reg .u32 ra;\n\t"
        "mapa.shared::cluster.u32 ra, %0, %1;\n\t"
        "st.shared::cluster.f32 [ra], %2;\n\t}"
        :: "r"(saddr), "r"(rank), "f"(v) : "memory");
}

__device__ __forceinline__ void cluster_sync_() {
    asm volatile("barrier.cluster.arrive.aligned;" ::: "memory");
    asm volatile("barrier.cluster.wait.aligned;" ::: "memory");
}

// ---------------- embedding ----------------
__global__ void embed_kernel(const int* __restrict__ words,
                             const float* __restrict__ emb,
                             float* __restrict__ x) {
    int i = blockIdx.x * blockDim.x + threadIdx.x;
    if (i < TT * EMBD) {
        int t = i / EMBD, k = i % EMBD;
        x[i] = emb[(size_t)words[t] * EMBD + k];
    }
}

// ---------------- input-projection GEMM ----------------
// out[dir][m][n] = sum_k A[m][k]*W_dir[n][k] + b_ih[n] + (n<1024 ? b_hh[n] : 0)
// (b_hh folded into the r,z pre-activations; the n-gate keeps b_hh separate
//  because it is multiplied by r inside the recurrence.)
#define BM 128
#define BN 128
#define BK 16

__global__ void __launch_bounds__(256) gemm_gi_kernel(
    const float* __restrict__ A, int M, int K,
    const float* __restrict__ Wf, const float* __restrict__ Wb,
    const float* __restrict__ bihf, const float* __restrict__ bhhf,
    const float* __restrict__ bihb, const float* __restrict__ bhhb,
    float* __restrict__ out)
{
    __shared__ float As[BK][BM + 4];
    __shared__ float Ws[BK][BN + 4];

    const int dir = blockIdx.z;
    const float* W   = dir ? Wb   : Wf;
    const float* bih = dir ? bihb : bihf;
    const float* bhh = dir ? bhhb : bhhf;

    const int n0 = blockIdx.x * BN;
    const int m0 = blockIdx.y * BM;
    const int tid = threadIdx.x;
    const int tx = tid & 15, ty = tid >> 4;

    float acc[8][8];
    #pragma unroll
    for (int i = 0; i < 8; i++)
        #pragma unroll
        for (int j = 0; j < 8; j++) acc[i][j] = 0.f;

    for (int k0 = 0; k0 < K; k0 += BK) {
        #pragma unroll
        for (int e = tid; e < BM * BK; e += 256) {
            int m = e >> 4, k = e & 15;
            int kk = k0 + k;
            As[k][m] = (kk < K) ? A[(size_t)(m0 + m) * K + kk] : 0.f;
        }
        #pragma unroll
        for (int e = tid; e < BN * BK; e += 256) {
            int n = e >> 4, k = e & 15;
            int kk = k0 + k;
            Ws[k][n] = (kk < K) ? W[(size_t)(n0 + n) * K + kk] : 0.f;
        }
        __syncthreads();
        #pragma unroll
        for (int k = 0; k < BK; k++) {
            float a[8], b[8];
            #pragma unroll
            for (int i = 0; i < 8; i++) a[i] = As[k][ty * 8 + i];
            #pragma unroll
            for (int i = 0; i < 8; i++) b[i] = Ws[k][tx * 8 + i];
            #pragma unroll
            for (int i = 0; i < 8; i++)
                #pragma unroll
                for (int j = 0; j < 8; j++)
                    acc[i][j] += a[i] * b[j];
        }
        __syncthreads();
    }

    #pragma unroll
    for (int i = 0; i < 8; i++) {
        int m = m0 + ty * 8 + i;
        #pragma unroll
        for (int j = 0; j < 8; j++) {
            int n = n0 + tx * 8 + j;
            float v = acc[i][j] + bih[n] + (n < 1024 ? bhh[n] : 0.f);
            out[(size_t)dir * M * G3 + (size_t)m * G3 + n] = v;
        }
    }
}

// ---------------- recurrent layer (one bidirectional layer) ----------------
// grid = 32 CTAs = 2 clusters of 16 (cluster 0: forward, cluster 1: backward).
// CTA crank owns h-outputs j in [32*crank, 32*crank+32). Its 96 W_hh rows
// (r,z,n for each owned j) live in SMEM fp32. Each of the 16 warps owns
// j0 = 32*crank + 2*warp and j0+1 (6 rows). Per step:
//   dot(6 rows x 512) from SMEM, warp butterfly reduce, gates on lanes 0/1,
//   broadcast the 2 new h values to all 16 CTAs' double-buffered h via
//   st.shared::cluster, then one cluster barrier.
__global__ void __launch_bounds__(512, 1) gru_layer_kernel(
    const float* __restrict__ gi,                 // [2][T][1536]
    const float* __restrict__ whf, const float* __restrict__ whb,
    const float* __restrict__ bhf, const float* __restrict__ bhb,
    float* __restrict__ y_out,                    // [T][1024], at [t][dir*512+j]
    float* __restrict__ state_out)                // [2][512]
{
    extern __shared__ float smem[];
    float* wsm  = smem;                 // 96*512 floats (192 KB)
    float* hbuf = smem + 96 * 512;      // 2*512 floats (double buffer)

    const int crank = blockIdx.x & 15;
    const int dir   = blockIdx.x >> 4;
    const int tid   = threadIdx.x;
    const int warp  = tid >> 5;
    const int lane  = tid & 31;

    const float* w_hh = dir ? whb : whf;
    const float* b_hh = dir ? bhb : bhf;
    const float* gid  = gi + (size_t)dir * TT * G3;

    const int j0 = crank * 32 + 2 * warp;

    // load weight slice: smem row (warp*6 + r6) = gate (r6%3) of j0 + (r6>=3)
    for (int rr = 0; rr < 96; rr++) {
        int wg = rr / 6, r6 = rr % 6;
        int jj = crank * 32 + 2 * wg + (r6 >= 3 ? 1 : 0);
        int grow = (r6 % 3) * HIDN + jj;
        wsm[rr * 512 + tid] = w_hh[(size_t)grow * HIDN + tid];
    }
    hbuf[tid] = 0.f;
    hbuf[512 + tid] = 0.f;
    float bhn = (lane < 2) ? b_hh[1024 + j0 + lane] : 0.f;

    __syncthreads();
    cluster_sync_();

    const unsigned hbase = (unsigned)__cvta_generic_to_shared(hbuf);

    for (int s = 0; s < TT; s++) {
        const int t   = dir ? (TT - 1 - s) : s;
        const int cur = s & 1;
        const int nxt = cur ^ 1;

        // per-step scalars for the two gate lanes (issued early; consumed
        // after the ~1.5k-cycle dot, hiding DRAM latency on the gi stream)
        float gi_r = 0.f, gi_z = 0.f, gi_n = 0.f, hprev = 0.f;
        if (lane < 2) {
            const float* g = gid + (size_t)t * G3;
            int j = j0 + lane;
            gi_r = g[j]; gi_z = g[512 + j]; gi_n = g[1024 + j];
            hprev = hbuf[cur * 512 + j];
        }

        const float4* h4 = (const float4*)(hbuf + cur * 512);
        float4 h0 = h4[lane], h1 = h4[lane + 32], h2 = h4[lane + 64], h3 = h4[lane + 96];

        float acc[6];
        #pragma unroll
        for (int r = 0; r < 6; r++) {
            const float4* wr = (const float4*)(wsm + (warp * 6 + r) * 512);
            float4 a = wr[lane], b = wr[lane + 32], c = wr[lane + 64], d = wr[lane + 96];
            float v;
            v  = a.x * h0.x; v += a.y * h0.y; v += a.z * h0.z; v += a.w * h0.w;
            v += b.x * h1.x; v += b.y * h1.y; v += b.z * h1.z; v += b.w * h1.w;
            v += c.x * h2.x; v += c.y * h2.y; v += c.z * h2.z; v += c.w * h2.w;
            v += d.x * h3.x; v += d.y * h3.y; v += d.z * h3.z; v += d.w * h3.w;
            acc[r] = v;
        }

        #pragma unroll
        for (int off = 16; off; off >>= 1) {
            #pragma unroll
            for (int r = 0; r < 6; r++)
                acc[r] += __shfl_xor_sync(0xffffffffu, acc[r], off);
        }

        float hnew = 0.f;
        if (lane < 2) {
            float rg = 1.f / (1.f + __expf(-(gi_r + acc[3 * lane + 0])));
            float zg = 1.f / (1.f + __expf(-(gi_z + acc[3 * lane + 1])));
            float u  = gi_n + rg * (acc[3 * lane + 2] + bhn);
            float e2 = __expf(2.f * u);
            float ng = 1.f - 2.f / (e2 + 1.f);     // tanh(u), inf-safe
            hnew = ng + zg * (hprev - ng);
            int j = j0 + lane;
            y_out[(size_t)t * 1024 + dir * 512 + j] = hnew;
            if (s == TT - 1) state_out[dir * 512 + j] = hnew;
        }

        // broadcast the warp's 2 new h values to all 16 CTAs (double buffer)
        float bv = __shfl_sync(0xffffffffu, hnew, (lane < 16) ? 0 : 1);
        int   jg = j0 + ((lane < 16) ? 0 : 1);
        st_remote_f32(hbase + (unsigned)((nxt * 512 + jg) * 4),
                      (unsigned)(lane & 15), bv);

        cluster_sync_();   // release/acquire: orders remote h stores + WAR
    }
}

// ---------------- launch ----------------
static void launch_gru(const float* gi,
                       const float* whf, const float* whb,
                       const float* bhf, const float* bhb,
                       float* y_out, float* state_out) {
    const size_t smem = (96 * 512 + 2 * 512) * sizeof(float);   // 200704 B
    cudaFuncSetAttribute(gru_layer_kernel,
                         cudaFuncAttributeMaxDynamicSharedMemorySize, (int)smem);
    cudaFuncSetAttribute(gru_layer_kernel,
                         cudaFuncAttributeNonPortableClusterSizeAllowed, 1);

    cudaLaunchConfig_t cfg = {};
    cfg.gridDim = dim3(32, 1, 1);
    cfg.blockDim = dim3(512, 1, 1);
    cfg.dynamicSmemBytes = smem;
    cfg.stream = 0;
    cudaLaunchAttribute attr[1];
    attr[0].id = cudaLaunchAttributeClusterDimension;
    attr[0].val.clusterDim.x = 16;
    attr[0].val.clusterDim.y = 1;
    attr[0].val.clusterDim.z = 1;
    cfg.attrs = attr;
    cfg.numAttrs = 1;

    cudaLaunchKernelEx(&cfg, gru_layer_kernel, gi, whf, whb, bhf, bhb, y_out, state_out);
}

extern "C" void kernel_launch(void* const* d_in, const int* in_sizes, int n_in,
                              void* d_out, int out_size) {
    const int*   words    = (const int*)d_in[0];
    const float* emb      = (const float*)d_in[1];
    const float* w_ih_l0f = (const float*)d_in[2];
    const float* w_hh_l0f = (const float*)d_in[3];
    const float* b_ih_l0f = (const float*)d_in[4];
    const float* b_hh_l0f = (const float*)d_in[5];
    const float* w_ih_l0b = (const float*)d_in[6];
    const float* w_hh_l0b = (const float*)d_in[7];
    const float* b_ih_l0b = (const float*)d_in[8];
    const float* b_hh_l0b = (const float*)d_in[9];
    const float* w_ih_l1f = (const float*)d_in[10];
    const float* w_hh_l1f = (const float*)d_in[11];
    const float* b_ih_l1f = (const float*)d_in[12];
    const float* b_hh_l1f = (const float*)d_in[13];
    const float* w_ih_l1b = (const float*)d_in[14];
    const float* w_hh_l1b = (const float*)d_in[15];
    const float* b_ih_l1b = (const float*)d_in[16];
    const float* b_hh_l1b = (const float*)d_in[17];
    float* out = (float*)d_out;

    float *px, *py0, *pgi0, *pgi1;
    cudaGetSymbolAddress((void**)&px,   g_x);
    cudaGetSymbolAddress((void**)&py0,  g_y0);
    cudaGetSymbolAddress((void**)&pgi0, g_gi0);
    cudaGetSymbolAddress((void**)&pgi1, g_gi1);

    // 1) embedding
    embed_kernel<<<(TT * EMBD + 255) / 256, 256>>>(words, emb, px);

    // 2) layer-0 input projections (both directions)
    dim3 gg(G3 / BN, TT / BM, 2);
    gemm_gi_kernel<<<gg, 256>>>(px, TT, EMBD,
                                w_ih_l0f, w_ih_l0b,
                                b_ih_l0f, b_hh_l0f, b_ih_l0b, b_hh_l0b, pgi0);

    // 3) layer-0 recurrence -> y0, states hf0/hb0
    launch_gru(pgi0, w_hh_l0f, w_hh_l0b, b_hh_l0f, b_hh_l0b,
               py0, out + (size_t)TT * 1024);

    // 4) layer-1 input projections
    gemm_gi_kernel<<<gg, 256>>>(py0, TT, 1024,
                                w_ih_l1f, w_ih_l1b,
                                b_ih_l1f, b_hh_l1f, b_ih_l1b, b_hh_l1b, pgi1);

    // 5) layer-1 recurrence -> output, states hf1/hb1
    launch_gru(pgi1, w_hh_l1f, w_hh_l1b, b_hh_l1f, b_hh_l1b,
               out, out + (size_t)TT * 1024 + 1024);
}

// round 3
// speedup vs baseline: 1.3510x; 1.3510x over previous
#include <cuda_runtime.h>
#include <cstdint>
#include <cstddef>

#define TT   4096
#define EMBD 100
#define HIDN 512
#define G3   1536

// ---------------- scratch (no cudaMalloc allowed) ----------------
__device__ float g_x[TT * EMBD];            // embedded inputs      (1.6 MB)
__device__ float g_y0[TT * 1024];           // layer-0 output       (16.8 MB)
__device__ float g_gi0[2 * TT * G3];        // layer-0 input gates  (50.3 MB)
__device__ float g_gi1[2 * TT * G3];        // layer-1 input gates  (50.3 MB)

// ---------------- helpers ----------------
__device__ __forceinline__ void st_remote_u64(unsigned saddr, unsigned rank,
                                              unsigned long long v) {
    asm volatile(
        "{\n\t.reg .u32 ra;\n\t"
        "mapa.shared::cluster.u32 ra, %0, %1;\n\t"
        "st.shared::cluster.u64 [ra], %2;\n\t}"
        :: "r"(saddr), "r"(rank), "l"(v) : "memory");
}

__device__ __forceinline__ void cluster_sync_() {
    asm volatile("barrier.cluster.arrive.aligned;" ::: "memory");
    asm volatile("barrier.cluster.wait.aligned;" ::: "memory");
}

// packed f32x2 fma: acc = w * h + acc   (lo,hi lanes independently, RN)
#define FMA2(acc, w, h) \
    asm("fma.rn.f32x2 %0, %1, %2, %0;" : "+l"(acc) : "l"(w), "l"(h))

__device__ __forceinline__ float lo_f(unsigned long long v) {
    return __int_as_float((int)(unsigned)(v & 0xffffffffull));
}
__device__ __forceinline__ float hi_f(unsigned long long v) {
    return __int_as_float((int)(unsigned)(v >> 32));
}

// ---------------- embedding ----------------
__global__ void embed_kernel(const int* __restrict__ words,
                             const float* __restrict__ emb,
                             float* __restrict__ x) {
    int i = blockIdx.x * blockDim.x + threadIdx.x;
    if (i < TT * EMBD) {
        int t = i / EMBD, k = i % EMBD;
        x[i] = emb[(size_t)words[t] * EMBD + k];
    }
}

// ---------------- input-projection GEMM ----------------
// out[dir][m][n] = sum_k A[m][k]*W_dir[n][k] + b_ih[n] + (n<1024 ? b_hh[n] : 0)
#define BM 128
#define BN 128
#define BK 16

__global__ void __launch_bounds__(256, 2) gemm_gi_kernel(
    const float* __restrict__ A, int M, int K,
    const float* __restrict__ Wf, const float* __restrict__ Wb,
    const float* __restrict__ bihf, const float* __restrict__ bhhf,
    const float* __restrict__ bihb, const float* __restrict__ bhhb,
    float* __restrict__ out)
{
    __shared__ float As[BK][BM + 4];
    __shared__ float Ws[BK][BN + 4];

    const int dir = blockIdx.z;
    const float* W   = dir ? Wb   : Wf;
    const float* bih = dir ? bihb : bihf;
    const float* bhh = dir ? bhhb : bhhf;

    const int n0 = blockIdx.x * BN;
    const int m0 = blockIdx.y * BM;
    const int tid = threadIdx.x;
    const int tx = tid & 15, ty = tid >> 4;

    float acc[8][8];
    #pragma unroll
    for (int i = 0; i < 8; i++)
        #pragma unroll
        for (int j = 0; j < 8; j++) acc[i][j] = 0.f;

    for (int k0 = 0; k0 < K; k0 += BK) {
        #pragma unroll
        for (int e = tid; e < BM * BK; e += 256) {
            int m = e >> 4, k = e & 15;
            int kk = k0 + k;
            As[k][m] = (kk < K) ? A[(size_t)(m0 + m) * K + kk] : 0.f;
        }
        #pragma unroll
        for (int e = tid; e < BN * BK; e += 256) {
            int n = e >> 4, k = e & 15;
            int kk = k0 + k;
            Ws[k][n] = (kk < K) ? W[(size_t)(n0 + n) * K + kk] : 0.f;
        }
        __syncthreads();
        #pragma unroll
        for (int k = 0; k < BK; k++) {
            float a[8], b[8];
            #pragma unroll
            for (int i = 0; i < 8; i++) a[i] = As[k][ty * 8 + i];
            #pragma unroll
            for (int i = 0; i < 8; i++) b[i] = Ws[k][tx * 8 + i];
            #pragma unroll
            for (int i = 0; i < 8; i++)
                #pragma unroll
                for (int j = 0; j < 8; j++)
                    acc[i][j] += a[i] * b[j];
        }
        __syncthreads();
    }

    #pragma unroll
    for (int i = 0; i < 8; i++) {
        int m = m0 + ty * 8 + i;
        #pragma unroll
        for (int j = 0; j < 8; j++) {
            int n = n0 + tx * 8 + j;
            float v = acc[i][j] + bih[n] + (n < 1024 ? bhh[n] : 0.f);
            out[(size_t)dir * M * G3 + (size_t)m * G3 + n] = v;
        }
    }
}

// ---------------- recurrent layer (one bidirectional layer) ----------------
// grid = 32 CTAs = 2 clusters of 16 (cluster 0: fwd, cluster 1: bwd).
// CTA crank owns h-outputs [32*crank, 32*crank+32). Each of 16 warps owns
// outputs j0=32*crank+2*warp, j0+1 (6 W_hh rows). ALL weights live in
// REGISTERS: per thread 48 packed f32x2 values (96 regs): row r (0..5),
// column-pairs (64p + 2*lane, +1) for p=0..7. Per step:
//   8x LDS.64 of h pairs -> 48 fma.rn.f32x2 -> horizontal add ->
//   butterfly reduce (30 shfl) -> gates on lanes 0/1 ->
//   st.shared::cluster.u64 broadcast of the warp's 2 outputs to 16 CTAs ->
//   one cluster barrier.
__global__ void __launch_bounds__(512, 1) gru_layer_kernel(
    const float* __restrict__ gi,                 // [2][T][1536]
    const float* __restrict__ whf, const float* __restrict__ whb,
    const float* __restrict__ bhf, const float* __restrict__ bhb,
    float* __restrict__ y_out,                    // [T][1024], at [t][dir*512+j]
    float* __restrict__ state_out)                // [2][512]
{
    __shared__ float hbuf[1024];                  // double-buffered h

    const int crank = blockIdx.x & 15;
    const int dir   = blockIdx.x >> 4;
    const int tid   = threadIdx.x;
    const int warp  = tid >> 5;
    const int lane  = tid & 31;

    const float* w_hh = dir ? whb : whf;
    const float* b_hh = dir ? bhb : bhf;
    const float* gid  = gi + (size_t)dir * TT * G3;

    const int j0 = crank * 32 + 2 * warp;

    // ---- load weight slice into registers (48 packed pairs = 96 regs) ----
    unsigned long long w[48];
    #pragma unroll
    for (int r = 0; r < 6; r++) {
        const int jj   = j0 + (r >= 3 ? 1 : 0);
        const int gate = r % 3;
        const float* base = w_hh + (size_t)(gate * HIDN + jj) * HIDN + 2 * lane;
        #pragma unroll
        for (int p = 0; p < 8; p++)
            w[r * 8 + p] = *(const unsigned long long*)(base + 64 * p);
    }

    hbuf[tid]       = 0.f;
    hbuf[512 + tid] = 0.f;
    const float bhn = (lane < 2) ? b_hh[1024 + j0 + lane] : 0.f;

    // gi pointer walk (lanes 0/1 only); prefetch step 0
    const int gstep = dir ? -G3 : G3;
    const float* gp = gid + (size_t)(dir ? TT - 1 : 0) * G3 + j0 + lane;
    float gr = 0.f, gz = 0.f, gn = 0.f;
    if (lane < 2) { gr = gp[0]; gz = gp[512]; gn = gp[1024]; }

    float* yp = y_out + (size_t)(dir ? TT - 1 : 0) * 1024 + dir * 512 + j0 + lane;
    const int ystep = dir ? -1024 : 1024;

    __syncthreads();
    cluster_sync_();

    const unsigned hbase = (unsigned)__cvta_generic_to_shared(hbuf);

    for (int s = 0; s < TT; s++) {
        const int cur = s & 1;
        const int nxt = cur ^ 1;

        float hprev = (lane < 2) ? hbuf[cur * 512 + j0 + lane] : 0.f;

        // prefetch gi for step s+1 (hidden behind the FMA block)
        float ngr = 0.f, ngz = 0.f, ngn = 0.f;
        if (lane < 2 && s + 1 < TT) {
            const float* g = gp + gstep;
            ngr = g[0]; ngz = g[512]; ngn = g[1024];
        }

        // ---- 48 packed FMAs against h pairs from SMEM ----
        const unsigned long long* h2 =
            (const unsigned long long*)(hbuf + cur * 512) + lane;
        unsigned long long a0 = 0, a1 = 0, a2 = 0, a3 = 0, a4 = 0, a5 = 0;
        #pragma unroll
        for (int p = 0; p < 8; p++) {
            unsigned long long hv = h2[32 * p];
            FMA2(a0, w[0 * 8 + p], hv);
            FMA2(a1, w[1 * 8 + p], hv);
            FMA2(a2, w[2 * 8 + p], hv);
            FMA2(a3, w[3 * 8 + p], hv);
            FMA2(a4, w[4 * 8 + p], hv);
            FMA2(a5, w[5 * 8 + p], hv);
        }
        float s0 = lo_f(a0) + hi_f(a0);
        float s1 = lo_f(a1) + hi_f(a1);
        float s2 = lo_f(a2) + hi_f(a2);
        float s3 = lo_f(a3) + hi_f(a3);
        float s4 = lo_f(a4) + hi_f(a4);
        float s5 = lo_f(a5) + hi_f(a5);

        #pragma unroll
        for (int off = 16; off; off >>= 1) {
            s0 += __shfl_xor_sync(0xffffffffu, s0, off);
            s1 += __shfl_xor_sync(0xffffffffu, s1, off);
            s2 += __shfl_xor_sync(0xffffffffu, s2, off);
            s3 += __shfl_xor_sync(0xffffffffu, s3, off);
            s4 += __shfl_xor_sync(0xffffffffu, s4, off);
            s5 += __shfl_xor_sync(0xffffffffu, s5, off);
        }

        float hnew = 0.f;
        if (lane < 2) {
            const float ar = lane ? s3 : s0;
            const float az = lane ? s4 : s1;
            const float an = lane ? s5 : s2;
            float rg = 1.f / (1.f + __expf(-(gr + ar)));
            float zg = 1.f / (1.f + __expf(-(gz + az)));
            float u  = gn + rg * (an + bhn);
            float e2 = __expf(2.f * u);
            float ng = 1.f - 2.f / (e2 + 1.f);      // tanh(u), inf-safe
            hnew = ng + zg * (hprev - ng);
            *yp = hnew;
            if (s == TT - 1) state_out[dir * 512 + j0 + lane] = hnew;
        }
        gr = ngr; gz = ngz; gn = ngn;
        gp += gstep; yp += ystep;

        // broadcast the warp's 2 new h values to all 16 CTAs (double buffer)
        const float v0 = __shfl_sync(0xffffffffu, hnew, 0);
        const float v1 = __shfl_sync(0xffffffffu, hnew, 1);
        if (lane < 16) {
            unsigned long long pk =
                ((unsigned long long)__float_as_uint(v1) << 32) |
                (unsigned long long)__float_as_uint(v0);
            st_remote_u64(hbase + (unsigned)((nxt * 512 + j0) * 4),
                          (unsigned)lane, pk);
        }

        cluster_sync_();   // release/acquire: orders remote h stores + WAR
    }
}

// ---------------- launch ----------------
static void launch_gru(const float* gi,
                       const float* whf, const float* whb,
                       const float* bhf, const float* bhb,
                       float* y_out, float* state_out) {
    cudaFuncSetAttribute(gru_layer_kernel,
                         cudaFuncAttributeNonPortableClusterSizeAllowed, 1);

    cudaLaunchConfig_t cfg = {};
    cfg.gridDim = dim3(32, 1, 1);
    cfg.blockDim = dim3(512, 1, 1);
    cfg.dynamicSmemBytes = 0;
    cfg.stream = 0;
    cudaLaunchAttribute attr[1];
    attr[0].id = cudaLaunchAttributeClusterDimension;
    attr[0].val.clusterDim.x = 16;
    attr[0].val.clusterDim.y = 1;
    attr[0].val.clusterDim.z = 1;
    cfg.attrs = attr;
    cfg.numAttrs = 1;

    cudaLaunchKernelEx(&cfg, gru_layer_kernel, gi, whf, whb, bhf, bhb, y_out, state_out);
}

extern "C" void kernel_launch(void* const* d_in, const int* in_sizes, int n_in,
                              void* d_out, int out_size) {
    const int*   words    = (const int*)d_in[0];
    const float* emb      = (const float*)d_in[1];
    const float* w_ih_l0f = (const float*)d_in[2];
    const float* w_hh_l0f = (const float*)d_in[3];
    const float* b_ih_l0f = (const float*)d_in[4];
    const float* b_hh_l0f = (const float*)d_in[5];
    const float* w_ih_l0b = (const float*)d_in[6];
    const float* w_hh_l0b = (const float*)d_in[7];
    const float* b_ih_l0b = (const float*)d_in[8];
    const float* b_hh_l0b = (const float*)d_in[9];
    const float* w_ih_l1f = (const float*)d_in[10];
    const float* w_hh_l1f = (const float*)d_in[11];
    const float* b_ih_l1f = (const float*)d_in[12];
    const float* b_hh_l1f = (const float*)d_in[13];
    const float* w_ih_l1b = (const float*)d_in[14];
    const float* w_hh_l1b = (const float*)d_in[15];
    const float* b_ih_l1b = (const float*)d_in[16];
    const float* b_hh_l1b = (const float*)d_in[17];
    float* out = (float*)d_out;

    float *px, *py0, *pgi0, *pgi1;
    cudaGetSymbolAddress((void**)&px,   g_x);
    cudaGetSymbolAddress((void**)&py0,  g_y0);
    cudaGetSymbolAddress((void**)&pgi0, g_gi0);
    cudaGetSymbolAddress((void**)&pgi1, g_gi1);

    // 1) embedding
    embed_kernel<<<(TT * EMBD + 255) / 256, 256>>>(words, emb, px);

    // 2) layer-0 input projections (both directions)
    dim3 gg(G3 / BN, TT / BM, 2);
    gemm_gi_kernel<<<gg, 256>>>(px, TT, EMBD,
                                w_ih_l0f, w_ih_l0b,
                                b_ih_l0f, b_hh_l0f, b_ih_l0b, b_hh_l0b, pgi0);

    // 3) layer-0 recurrence -> y0, states hf0/hb0
    launch_gru(pgi0, w_hh_l0f, w_hh_l0b, b_hh_l0f, b_hh_l0b,
               py0, out + (size_t)TT * 1024);

    // 4) layer-1 input projections
    gemm_gi_kernel<<<gg, 256>>>(py0, TT, 1024,
                                w_ih_l1f, w_ih_l1b,
                                b_ih_l1f, b_hh_l1f, b_ih_l1b, b_hh_l1b, pgi1);

    // 5) layer-1 recurrence -> output, states hf1/hb1
    launch_gru(pgi1, w_hh_l1f, w_hh_l1b, b_hh_l1f, b_hh_l1b,
               out, out + (size_t)TT * 1024 + 1024);
}

// round 5
// speedup vs baseline: 1.6805x; 1.2439x over previous
#include <cuda_runtime.h>
#include <cstdint>
#include <cstddef>

#define TT   4096
#define EMBD 100
#define HIDN 512
#define G3   1536

// ---------------- scratch (no cudaMalloc allowed) ----------------
__device__ float g_x[TT * EMBD];            // embedded inputs      (1.6 MB)
__device__ float g_y0[TT * 1024];           // layer-0 output       (16.8 MB)
__device__ float g_gi0[2 * TT * G3];        // layer-0 input gates  (50.3 MB)
__device__ float g_gi1[2 * TT * G3];        // layer-1 input gates  (50.3 MB)

// ---------------- helpers ----------------
__device__ __forceinline__ void cluster_sync_() {
    asm volatile("barrier.cluster.arrive.aligned;" ::: "memory");
    asm volatile("barrier.cluster.wait.aligned;" ::: "memory");
}

// remote store + transaction-complete on the remote CTA's mbarrier
__device__ __forceinline__ void st_async_u64(unsigned daddr, unsigned mbaddr,
                                             unsigned rank, unsigned long long v) {
    asm volatile(
        "{\n\t.reg .u32 ra, rb;\n\t"
        "mapa.shared::cluster.u32 ra, %0, %2;\n\t"
        "mapa.shared::cluster.u32 rb, %1, %2;\n\t"
        "st.async.shared::cluster.mbarrier::complete_tx::bytes.u64 [ra], %3, [rb];\n\t"
        "}"
        :: "r"(daddr), "r"(mbaddr), "r"(rank), "l"(v) : "memory");
}

__device__ __forceinline__ void mbar_init(unsigned mb, unsigned cnt) {
    asm volatile("mbarrier.init.shared.b64 [%0], %1;" :: "r"(mb), "r"(cnt) : "memory");
}
__device__ __forceinline__ void mbar_arm(unsigned mb, unsigned tx) {
    asm volatile("mbarrier.arrive.expect_tx.shared.b64 _, [%0], %1;"
                 :: "r"(mb), "r"(tx) : "memory");
}
__device__ __forceinline__ void mbar_wait(unsigned mb, unsigned par) {
    unsigned done;
    asm volatile(
        "{\n\t.reg .pred p;\n\t"
        "mbarrier.try_wait.parity.acquire.cluster.shared::cta.b64 p, [%1], %2;\n\t"
        "selp.b32 %0, 1, 0, p;\n\t}"
        : "=r"(done) : "r"(mb), "r"(par) : "memory");
    while (!done) {
        asm volatile(
            "{\n\t.reg .pred p;\n\t"
            "mbarrier.try_wait.parity.acquire.cluster.shared::cta.b64 p, [%1], %2, 0x989680;\n\t"
            "selp.b32 %0, 1, 0, p;\n\t}"
            : "=r"(done) : "r"(mb), "r"(par) : "memory");
    }
}

// packed f32x2 fma: acc = w * h + acc
#define FMA2(acc, w, h) \
    asm("fma.rn.f32x2 %0, %1, %2, %0;" : "+l"(acc) : "l"(w), "l"(h))

__device__ __forceinline__ float lo_f(unsigned long long v) {
    return __int_as_float((int)(unsigned)(v & 0xffffffffull));
}
__device__ __forceinline__ float hi_f(unsigned long long v) {
    return __int_as_float((int)(unsigned)(v >> 32));
}

// ---------------- embedding ----------------
__global__ void embed_kernel(const int* __restrict__ words,
                             const float* __restrict__ emb,
                             float* __restrict__ x) {
    int i = blockIdx.x * blockDim.x + threadIdx.x;
    if (i < TT * EMBD) {
        int t = i / EMBD, k = i % EMBD;
        x[i] = emb[(size_t)words[t] * EMBD + k];
    }
}

// ---------------- input-projection GEMM ----------------
#define BM 128
#define BN 128
#define BK 16

__global__ void __launch_bounds__(256, 2) gemm_gi_kernel(
    const float* __restrict__ A, int M, int K,
    const float* __restrict__ Wf, const float* __restrict__ Wb,
    const float* __restrict__ bihf, const float* __restrict__ bhhf,
    const float* __restrict__ bihb, const float* __restrict__ bhhb,
    float* __restrict__ out)
{
    __shared__ float As[BK][BM + 4];
    __shared__ float Ws[BK][BN + 4];

    const int dir = blockIdx.z;
    const float* W   = dir ? Wb   : Wf;
    const float* bih = dir ? bihb : bihf;
    const float* bhh = dir ? bhhb : bhhf;

    const int n0 = blockIdx.x * BN;
    const int m0 = blockIdx.y * BM;
    const int tid = threadIdx.x;
    const int tx = tid & 15, ty = tid >> 4;

    float acc[8][8];
    #pragma unroll
    for (int i = 0; i < 8; i++)
        #pragma unroll
        for (int j = 0; j < 8; j++) acc[i][j] = 0.f;

    for (int k0 = 0; k0 < K; k0 += BK) {
        #pragma unroll
        for (int e = tid; e < BM * BK; e += 256) {
            int m = e >> 4, k = e & 15;
            int kk = k0 + k;
            As[k][m] = (kk < K) ? A[(size_t)(m0 + m) * K + kk] : 0.f;
        }
        #pragma unroll
        for (int e = tid; e < BN * BK; e += 256) {
            int n = e >> 4, k = e & 15;
            int kk = k0 + k;
            Ws[k][n] = (kk < K) ? W[(size_t)(n0 + n) * K + kk] : 0.f;
        }
        __syncthreads();
        #pragma unroll
        for (int k = 0; k < BK; k++) {
            float a[8], b[8];
            #pragma unroll
            for (int i = 0; i < 8; i++) a[i] = As[k][ty * 8 + i];
            #pragma unroll
            for (int i = 0; i < 8; i++) b[i] = Ws[k][tx * 8 + i];
            #pragma unroll
            for (int i = 0; i < 8; i++)
                #pragma unroll
                for (int j = 0; j < 8; j++)
                    acc[i][j] += a[i] * b[j];
        }
        __syncthreads();
    }

    #pragma unroll
    for (int i = 0; i < 8; i++) {
        int m = m0 + ty * 8 + i;
        #pragma unroll
        for (int j = 0; j < 8; j++) {
            int n = n0 + tx * 8 + j;
            float v = acc[i][j] + bih[n] + (n < 1024 ? bhh[n] : 0.f);
            out[(size_t)dir * M * G3 + (size_t)m * G3 + n] = v;
        }
    }
}

// ---------------- recurrent layer (one bidirectional layer) ----------------
// 32 CTAs = 2 clusters of 16 (fwd / bwd). CTA crank owns h[32*crank..+32).
// Weights register-resident (48 f32x2 pairs / thread). Per step:
//   mbarrier try_wait (remote stores of prev step) -> 8x LDS.64 h ->
//   48 fma.rn.f32x2 -> 30-shfl butterfly -> gates on lanes 0..15 ->
//   shfl_xor(1) pair-up -> st.async.u64 to all 16 CTAs with complete_tx.
// No cluster barrier inside the loop.
__global__ void __launch_bounds__(512, 1) gru_layer_kernel(
    const float* __restrict__ gi,                 // [2][T][1536]
    const float* __restrict__ whf, const float* __restrict__ whb,
    const float* __restrict__ bhf, const float* __restrict__ bhb,
    float* __restrict__ y_out,                    // [T][1024]
    float* __restrict__ state_out)                // [2][512]
{
    __shared__ float hbuf[1024];                          // double-buffered h
    __shared__ __align__(8) unsigned long long mbar[2];   // one per buffer

    const int crank = blockIdx.x & 15;
    const int dir   = blockIdx.x >> 4;
    const int tid   = threadIdx.x;
    const int warp  = tid >> 5;
    const int lane  = tid & 31;

    const float* w_hh = dir ? whb : whf;
    const float* b_hh = dir ? bhb : bhf;
    const float* gid  = gi + (size_t)dir * TT * G3;

    const int j0 = crank * 32 + 2 * warp;
    const int o  = lane & 1;              // which of the 2 outputs this lane gates

    // ---- weights into registers: 48 packed f32x2 (96 regs) ----
    unsigned long long w[48];
    #pragma unroll
    for (int r = 0; r < 6; r++) {
        const int jj   = j0 + (r >= 3 ? 1 : 0);
        const int gate = r % 3;
        const float* base = w_hh + (size_t)(gate * HIDN + jj) * HIDN + 2 * lane;
        #pragma unroll
        for (int p = 0; p < 8; p++)
            w[r * 8 + p] = *(const unsigned long long*)(base + 64 * p);
    }

    hbuf[tid]       = 0.f;
    hbuf[512 + tid] = 0.f;
    const float bhn = (lane < 16) ? b_hh[1024 + j0 + o] : 0.f;

    const unsigned hbase = (unsigned)__cvta_generic_to_shared(hbuf);
    const unsigned mbase = (unsigned)__cvta_generic_to_shared(mbar);
    const unsigned TXB   = 16u * 16u * 8u;      // bytes into each buffer per step

    if (tid == 0) {
        mbar_init(mbase, 1);
        mbar_init(mbase + 8, 1);
        mbar_arm(mbase + 8, TXB);               // buffer 1 <- step-0 stores
    }

    // gi walk (lanes 0..15 load the 2 owned gate scalars, per output o)
    const int gstep = dir ? -G3 : G3;
    const float* gp = gid + (size_t)(dir ? TT - 1 : 0) * G3 + j0 + o;
    float gr = 0.f, gz = 0.f, gn = 0.f;
    if (lane < 16) { gr = gp[0]; gz = gp[512]; gn = gp[1024]; }

    float* yp = y_out + (size_t)(dir ? TT - 1 : 0) * 1024 + dir * 512 + j0 + lane;
    const int ystep = dir ? -1024 : 1024;

    __syncthreads();
    cluster_sync_();    // mbarriers + hbuf zeros visible cluster-wide

    for (int s = 0; s < TT; s++) {
        const int cur = s & 1;
        const int nxt = cur ^ 1;
        const unsigned mb_cur = mbase + (unsigned)(cur * 8);

        if (s > 0) mbar_wait(mb_cur, ((unsigned)(s - 1) >> 1) & 1u);
        if (tid == 0) mbar_arm(mb_cur, TXB);    // re-arm for step-(s+1) stores

        float hprev = (lane < 16) ? hbuf[cur * 512 + j0 + o] : 0.f;

        // ---- 48 packed FMAs against h pairs from SMEM ----
        const unsigned long long* h2 =
            (const unsigned long long*)(hbuf + cur * 512) + lane;
        unsigned long long a0 = 0, a1 = 0, a2 = 0, a3 = 0, a4 = 0, a5 = 0;
        #pragma unroll
        for (int p = 0; p < 8; p++) {
            unsigned long long hv = h2[32 * p];
            FMA2(a0, w[0 * 8 + p], hv);
            FMA2(a1, w[1 * 8 + p], hv);
            FMA2(a2, w[2 * 8 + p], hv);
            FMA2(a3, w[3 * 8 + p], hv);
            FMA2(a4, w[4 * 8 + p], hv);
            FMA2(a5, w[5 * 8 + p], hv);
        }

        float s0 = lo_f(a0) + hi_f(a0);
        float s1 = lo_f(a1) + hi_f(a1);
        float s2 = lo_f(a2) + hi_f(a2);
        float s3 = lo_f(a3) + hi_f(a3);
        float s4 = lo_f(a4) + hi_f(a4);
        float s5 = lo_f(a5) + hi_f(a5);

        #pragma unroll
        for (int off = 16; off; off >>= 1) {
            s0 += __shfl_xor_sync(0xffffffffu, s0, off);
            s1 += __shfl_xor_sync(0xffffffffu, s1, off);
            s2 += __shfl_xor_sync(0xffffffffu, s2, off);
            s3 += __shfl_xor_sync(0xffffffffu, s3, off);
            s4 += __shfl_xor_sync(0xffffffffu, s4, off);
            s5 += __shfl_xor_sync(0xffffffffu, s5, off);
        }

        float hnew = 0.f;
        if (lane < 16) {
            const float ar = o ? s3 : s0;
            const float az = o ? s4 : s1;
            const float an = o ? s5 : s2;
            float rg = 1.f / (1.f + __expf(-(gr + ar)));
            float zg = 1.f / (1.f + __expf(-(gz + az)));
            float u  = gn + rg * (an + bhn);
            float e2 = __expf(2.f * u);
            float ng = 1.f - 2.f / (e2 + 1.f);       // tanh(u), inf-safe
            hnew = ng + zg * (hprev - ng);
        }

        // pair-up: each of lanes 0..15 gets both outputs, stores to rank=lane
        const float hpart = __shfl_xor_sync(0xffffffffu, hnew, 1);
        if (lane < 16 && s + 1 < TT) {
            const float v0 = o ? hpart : hnew;
            const float v1 = o ? hnew  : hpart;
            unsigned long long pk =
                ((unsigned long long)__float_as_uint(v1) << 32) |
                (unsigned long long)__float_as_uint(v0);
            st_async_u64(hbase + (unsigned)((nxt * 512 + j0) * 4),
                         mbase + (unsigned)(nxt * 8),
                         (unsigned)lane, pk);
        }

        if (lane < 2) {
            *yp = hnew;
            if (s == TT - 1) state_out[dir * 512 + j0 + lane] = hnew;
        }

        // load gi for next step (latency hidden under inter-step wait)
        if (lane < 16 && s + 1 < TT) {
            const float* g = gp + gstep;
            gr = g[0]; gz = g[512]; gn = g[1024];
        }
        gp += gstep; yp += ystep;
    }

    cluster_sync_();    // keep smem alive until every in-flight store landed
}

// ---------------- launch ----------------
static void launch_gru(const float* gi,
                       const float* whf, const float* whb,
                       const float* bhf, const float* bhb,
                       float* y_out, float* state_out) {
    cudaFuncSetAttribute(gru_layer_kernel,
                         cudaFuncAttributeNonPortableClusterSizeAllowed, 1);

    cudaLaunchConfig_t cfg = {};
    cfg.gridDim = dim3(32, 1, 1);
    cfg.blockDim = dim3(512, 1, 1);
    cfg.dynamicSmemBytes = 0;
    cfg.stream = 0;
    cudaLaunchAttribute attr[1];
    attr[0].id = cudaLaunchAttributeClusterDimension;
    attr[0].val.clusterDim.x = 16;
    attr[0].val.clusterDim.y = 1;
    attr[0].val.clusterDim.z = 1;
    cfg.attrs = attr;
    cfg.numAttrs = 1;

    cudaLaunchKernelEx(&cfg, gru_layer_kernel, gi, whf, whb, bhf, bhb, y_out, state_out);
}

extern "C" void kernel_launch(void* const* d_in, const int* in_sizes, int n_in,
                              void* d_out, int out_size) {
    const int*   words    = (const int*)d_in[0];
    const float* emb      = (const float*)d_in[1];
    const float* w_ih_l0f = (const float*)d_in[2];
    const float* w_hh_l0f = (const float*)d_in[3];
    const float* b_ih_l0f = (const float*)d_in[4];
    const float* b_hh_l0f = (const float*)d_in[5];
    const float* w_ih_l0b = (const float*)d_in[6];
    const float* w_hh_l0b = (const float*)d_in[7];
    const float* b_ih_l0b = (const float*)d_in[8];
    const float* b_hh_l0b = (const float*)d_in[9];
    const float* w_ih_l1f = (const float*)d_in[10];
    const float* w_hh_l1f = (const float*)d_in[11];
    const float* b_ih_l1f = (const float*)d_in[12];
    const float* b_hh_l1f = (const float*)d_in[13];
    const float* w_ih_l1b = (const float*)d_in[14];
    const float* w_hh_l1b = (const float*)d_in[15];
    const float* b_ih_l1b = (const float*)d_in[16];
    const float* b_hh_l1b = (const float*)d_in[17];
    float* out = (float*)d_out;

    float *px, *py0, *pgi0, *pgi1;
    cudaGetSymbolAddress((void**)&px,   g_x);
    cudaGetSymbolAddress((void**)&py0,  g_y0);
    cudaGetSymbolAddress((void**)&pgi0, g_gi0);
    cudaGetSymbolAddress((void**)&pgi1, g_gi1);

    // 1) embedding
    embed_kernel<<<(TT * EMBD + 255) / 256, 256>>>(words, emb, px);

    // 2) layer-0 input projections (both directions)
    dim3 gg(G3 / BN, TT / BM, 2);
    gemm_gi_kernel<<<gg, 256>>>(px, TT, EMBD,
                                w_ih_l0f, w_ih_l0b,
                                b_ih_l0f, b_hh_l0f, b_ih_l0b, b_hh_l0b, pgi0);

    // 3) layer-0 recurrence
    launch_gru(pgi0, w_hh_l0f, w_hh_l0b, b_hh_l0f, b_hh_l0b,
               py0, out + (size_t)TT * 1024);

    // 4) layer-1 input projections
    gemm_gi_kernel<<<gg, 256>>>(py0, TT, 1024,
                                w_ih_l1f, w_ih_l1b,
                                b_ih_l1f, b_hh_l1f, b_ih_l1b, b_hh_l1b, pgi1);

    // 5) layer-1 recurrence
    launch_gru(pgi1, w_hh_l1f, w_hh_l1b, b_hh_l1f, b_hh_l1b,
               out, out + (size_t)TT * 1024 + 1024);
}